// round 4
// baseline (speedup 1.0000x reference)
#include <cuda_runtime.h>

// Problem constants
constexpr int CB   = 2;
constexpr int CS   = 2048;
constexpr int CH   = 1024;
constexpr int CNH  = 16;
constexpr int CNKV = 4;
constexpr int CHD  = 64;
constexpr int CM   = CB * CS;        // 4096 rows

// Scratch (no cudaMalloc allowed)
__device__ float g_q[(size_t)CB * CS * CNH * CHD];     // 16 MB
__device__ float g_k[(size_t)CB * CS * CNKV * CHD];    // 4 MB
__device__ float g_v[(size_t)CB * CS * CNKV * CHD];    // 4 MB
__device__ float g_attn[(size_t)CB * CS * CNH * CHD];  // 16 MB

// ---------------------------------------------------------------------------
// tf32 helpers
// ---------------------------------------------------------------------------
__device__ __forceinline__ unsigned f2tf(float x) {
    unsigned u;
    asm("cvt.rna.tf32.f32 %0, %1;" : "=r"(u) : "f"(x));
    return u;
}

// 3xTF32 split: x ~= hi + lo, both representable in tf32.
__device__ __forceinline__ void split_tf(float x, unsigned& hi, unsigned& lo) {
    hi = f2tf(x);
    lo = f2tf(x - __uint_as_float(hi));
}

__device__ __forceinline__ void mma_tf32(float d[4], const unsigned a[4],
                                         const unsigned b[2]) {
    asm volatile(
        "mma.sync.aligned.m16n8k8.row.col.f32.tf32.tf32.f32 "
        "{%0,%1,%2,%3}, {%4,%5,%6,%7}, {%8,%9}, {%0,%1,%2,%3};"
        : "+f"(d[0]), "+f"(d[1]), "+f"(d[2]), "+f"(d[3])
        : "r"(a[0]), "r"(a[1]), "r"(a[2]), "r"(a[3]), "r"(b[0]), "r"(b[1]));
}

// ---------------------------------------------------------------------------
// GEMM via 3xTF32 mma: C = A(MxK) @ B(KxN), row-major fp32 in/out, ~fp32 acc.
// Block tile 128x128, BK=16, 256 threads = 8 warps (2x4), warp tile 64x32.
// ---------------------------------------------------------------------------
__global__ __launch_bounds__(256) void gemm_tf32_kernel(
    int M, int N, int K,
    const float* __restrict__ A, const float* __restrict__ Bm,
    float* __restrict__ C)
{
    // layout: [mfb(8)][ks(2)][lane(32)][reg(4)] ; B: [nfb(16)][ks(2)][lane(32)][reg(2)]
    __shared__ unsigned sAh[2048], sAl[2048];
    __shared__ unsigned sBh[2048], sBl[2048];

    const int tid  = threadIdx.x;
    const int lane = tid & 31;
    const int w    = tid >> 5;
    const int wm   = w >> 2;          // 0..1
    const int wn   = w & 3;           // 0..3
    const int g    = lane >> 2;       // 0..7
    const int t    = lane & 3;        // 0..3
    const int brow = blockIdx.y, bcol = blockIdx.x;

    A  += (size_t)brow * 128 * K;
    Bm += (size_t)bcol * 128;
    C  += (size_t)brow * 128 * N + (size_t)bcol * 128;

    float acc[4][4][4];
#pragma unroll
    for (int i = 0; i < 4; i++)
#pragma unroll
        for (int j = 0; j < 4; j++)
#pragma unroll
            for (int r = 0; r < 4; r++) acc[i][j][r] = 0.f;

    const int aRow = tid >> 1;             // 0..127
    const int aK0  = (tid & 1) * 8;        // 0 or 8
    const int bK   = tid >> 4;             // 0..15
    const int bC0  = (tid & 15) * 8;       // 0..120

    for (int k0 = 0; k0 < K; k0 += 16) {
        __syncthreads();
        // --- stage A (128x16) into fragment layout, split hi/lo ---
#pragma unroll
        for (int h4 = 0; h4 < 2; h4++) {
            float4 a4 = *(const float4*)(A + (size_t)aRow * K + k0 + aK0 + h4 * 4);
            float av[4] = {a4.x, a4.y, a4.z, a4.w};
            int mfb = aRow >> 4, rr = aRow & 15;
#pragma unroll
            for (int e = 0; e < 4; e++) {
                int kk = aK0 + h4 * 4 + e;
                int ln = (rr & 7) * 4 + (kk & 3);
                int rg = (rr >> 3) + 2 * ((kk & 7) >> 2);
                int ks = kk >> 3;
                unsigned hi, lo;
                split_tf(av[e], hi, lo);
                int idx = ((mfb * 2 + ks) * 32 + ln) * 4 + rg;
                sAh[idx] = hi;
                sAl[idx] = lo;
            }
        }
        // --- stage B (16x128) into fragment layout, split hi/lo ---
#pragma unroll
        for (int h4 = 0; h4 < 2; h4++) {
            float4 b4 = *(const float4*)(Bm + (size_t)(k0 + bK) * N + bC0 + h4 * 4);
            float bv[4] = {b4.x, b4.y, b4.z, b4.w};
#pragma unroll
            for (int e = 0; e < 4; e++) {
                int col = bC0 + h4 * 4 + e;
                int nfb = col >> 3;
                int ln  = (col & 7) * 4 + (bK & 3);
                int rg  = (bK & 7) >> 2;
                int ks  = bK >> 3;
                unsigned hi, lo;
                split_tf(bv[e], hi, lo);
                int idx = ((nfb * 2 + ks) * 32 + ln) * 2 + rg;
                sBh[idx] = hi;
                sBl[idx] = lo;
            }
        }
        __syncthreads();

        // --- compute: 3xTF32 ---
#pragma unroll
        for (int ks = 0; ks < 2; ks++) {
            unsigned aH[4][4], aL[4][4];
            unsigned bH[4][2], bL[4][2];
#pragma unroll
            for (int mf = 0; mf < 4; mf++) {
                int idx = (((wm * 4 + mf) * 2 + ks) * 32 + lane) * 4;
                uint4 vh = *(const uint4*)&sAh[idx];
                uint4 vl = *(const uint4*)&sAl[idx];
                aH[mf][0] = vh.x; aH[mf][1] = vh.y; aH[mf][2] = vh.z; aH[mf][3] = vh.w;
                aL[mf][0] = vl.x; aL[mf][1] = vl.y; aL[mf][2] = vl.z; aL[mf][3] = vl.w;
            }
#pragma unroll
            for (int nf = 0; nf < 4; nf++) {
                int idx = (((wn * 4 + nf) * 2 + ks) * 32 + lane) * 2;
                uint2 vh = *(const uint2*)&sBh[idx];
                uint2 vl = *(const uint2*)&sBl[idx];
                bH[nf][0] = vh.x; bH[nf][1] = vh.y;
                bL[nf][0] = vl.x; bL[nf][1] = vl.y;
            }
#pragma unroll
            for (int mf = 0; mf < 4; mf++)
#pragma unroll
                for (int nf = 0; nf < 4; nf++) {
                    mma_tf32(acc[mf][nf], aL[mf], bH[nf]);
                    mma_tf32(acc[mf][nf], aH[mf], bL[nf]);
                    mma_tf32(acc[mf][nf], aH[mf], bH[nf]);
                }
        }
    }

    // --- epilogue ---
#pragma unroll
    for (int mf = 0; mf < 4; mf++) {
        int row0 = wm * 64 + mf * 16 + g;
#pragma unroll
        for (int nf = 0; nf < 4; nf++) {
            int col = wn * 32 + nf * 8 + 2 * t;
            *(float2*)(C + (size_t)row0 * N + col) =
                make_float2(acc[mf][nf][0], acc[mf][nf][1]);
            *(float2*)(C + (size_t)(row0 + 8) * N + col) =
                make_float2(acc[mf][nf][2], acc[mf][nf][3]);
        }
    }
}

// ---------------------------------------------------------------------------
// RoPE (half-rotation). Each thread handles a (d, d+32) pair -> race-free.
// ---------------------------------------------------------------------------
__global__ void rope_kernel(float* __restrict__ x, const float* __restrict__ cosp,
                            const float* __restrict__ sinp, int nheads)
{
    int idx = blockIdx.x * blockDim.x + threadIdx.x;
    int total = CB * CS * nheads * (CHD / 2);
    if (idx >= total) return;
    int d = idx & 31;
    int tt = idx >> 5;
    int s = (tt / nheads) % CS;
    float* p = x + (size_t)tt * CHD;
    float x0 = p[d];
    float x1 = p[d + 32];
    float c0 = cosp[s * CHD + d],      s0 = sinp[s * CHD + d];
    float c1 = cosp[s * CHD + d + 32], s1 = sinp[s * CHD + d + 32];
    p[d]      = x0 * c0 - x1 * s0;
    p[d + 32] = x1 * c1 + x0 * s1;
}

// ---------------------------------------------------------------------------
// Flash attention with tf32 mma. Q tile = 128 rows, KV tile = 64.
// S = Q@K^T uses 3xTF32 (scores feed exp -> need accuracy).
// O += P@V uses single tf32 (P in [0,1]; error scales with weights).
// 8 warps; warp w owns q rows [w*16, w*16+16).
// smem (u32/floats): sQh 8192 | sQl 8192 | sKh 4096 | sKl 4096 | sV 4096 |
//                    sP 8192 | sMask 64  = 36928 floats = 147,712 B
// ---------------------------------------------------------------------------
constexpr int ATT_SMEM_FLOATS = 8192 + 8192 + 4096 + 4096 + 4096 + 8192 + 64;
constexpr int ATT_SMEM_BYTES  = ATT_SMEM_FLOATS * 4;

__global__ __launch_bounds__(256) void attn_mma_kernel(
    const float* __restrict__ q, const float* __restrict__ k,
    const float* __restrict__ v, const float* __restrict__ amask,
    float* __restrict__ out)
{
    extern __shared__ float smf[];
    unsigned* sQh = (unsigned*)smf;                  // 8192
    unsigned* sQl = (unsigned*)(smf + 8192);         // 8192
    unsigned* sKh = (unsigned*)(smf + 16384);        // 4096
    unsigned* sKl = (unsigned*)(smf + 20480);        // 4096
    unsigned* sV  = (unsigned*)(smf + 24576);        // 4096
    unsigned* sP  = (unsigned*)(smf + 28672);        // 8192
    float*    sMask = smf + 36864;                   // 64

    const int tid  = threadIdx.x;
    const int lane = tid & 31;
    const int w    = tid >> 5;
    const int g    = lane >> 2;
    const int t    = lane & 3;
    const int mt = blockIdx.x, h = blockIdx.y, b = blockIdx.z;
    const int grp = h >> 2;           // NKV group (R = 4)
    const int m0 = mt * 128;

    // --- stage Q tile (128 x 64) into per-warp A-fragment layout (hi/lo) ---
#pragma unroll
    for (int i = 0; i < 8; i++) {
        int idx = tid + i * 256;      // float4 index over 128x16
        int r = idx >> 4, k4 = (idx & 15) * 4;
        float4 qv = *(const float4*)(
            q + (((size_t)b * CS + m0 + r) * CNH + h) * CHD + k4);
        float qa[4] = {qv.x, qv.y, qv.z, qv.w};
        int wq = r >> 4, rr = r & 15;
#pragma unroll
        for (int e = 0; e < 4; e++) {
            int kk = k4 + e;
            int ln = (rr & 7) * 4 + (kk & 3);
            int rg = (rr >> 3) + 2 * ((kk & 7) >> 2);
            int ks = kk >> 3;
            unsigned hi, lo;
            split_tf(qa[e], hi, lo);
            int sidx = ((wq * 8 + ks) * 32 + ln) * 4 + rg;
            sQh[sidx] = hi;
            sQl[sidx] = lo;
        }
    }

    float o[8][4];
    float m_i[2] = {-1e30f, -1e30f};
    float l_i[2] = {0.f, 0.f};
#pragma unroll
    for (int nf = 0; nf < 8; nf++)
#pragma unroll
        for (int r = 0; r < 4; r++) o[nf][r] = 0.f;

    const int ntmax = 2 * mt + 1;
    for (int nt = 0; nt <= ntmax; nt++) {
        const int n0 = nt * 64;
        __syncthreads();
        // --- stage K (hi/lo B-frag) and V (single B-frag) ---
#pragma unroll
        for (int i = 0; i < 4; i++) {
            int idx = tid + i * 256;          // float4 index over 64x16
            int r = idx >> 4, k4 = (idx & 15) * 4;
            size_t gbase = (((size_t)b * CS + n0 + r) * CNKV + grp) * CHD + k4;
            float4 kv4 = *(const float4*)(k + gbase);
            float4 vv4 = *(const float4*)(v + gbase);
            float ka[4] = {kv4.x, kv4.y, kv4.z, kv4.w};
            float va[4] = {vv4.x, vv4.y, vv4.z, vv4.w};
#pragma unroll
            for (int e = 0; e < 4; e++) {
                int kk = k4 + e;
                // K element (n = r, k = kk)
                int kidx = (((r >> 3) * 8 + (kk >> 3)) * 32 + (r & 7) * 4 + (kk & 3)) * 2 +
                           ((kk & 7) >> 2);
                unsigned hi, lo;
                split_tf(ka[e], hi, lo);
                sKh[kidx] = hi;
                sKl[kidx] = lo;
                // V element (k = r, n = kk)
                sV[(((kk >> 3) * 8 + (r >> 3)) * 32 + (kk & 7) * 4 + (r & 3)) * 2 +
                   ((r & 7) >> 2)] = f2tf(va[e]);
            }
        }
        if (tid < 64)
            sMask[tid] = (1.0f - amask[(size_t)b * CS + n0 + tid]) * -1e9f;
        __syncthreads();

        // --- S = Q @ K^T (3xTF32): per warp 16 x 64 ---
        float s[8][4];
#pragma unroll
        for (int nf = 0; nf < 8; nf++)
#pragma unroll
            for (int r = 0; r < 4; r++) s[nf][r] = 0.f;

#pragma unroll
        for (int ks = 0; ks < 8; ks++) {
            unsigned aH[4], aL[4];
            int aidx = ((w * 8 + ks) * 32 + lane) * 4;
            const uint4 avh = *(const uint4*)&sQh[aidx];
            const uint4 avl = *(const uint4*)&sQl[aidx];
            aH[0] = avh.x; aH[1] = avh.y; aH[2] = avh.z; aH[3] = avh.w;
            aL[0] = avl.x; aL[1] = avl.y; aL[2] = avl.z; aL[3] = avl.w;
#pragma unroll
            for (int nf = 0; nf < 8; nf++) {
                unsigned bH[2], bL[2];
                int bidx = ((nf * 8 + ks) * 32 + lane) * 2;
                const uint2 bvh = *(const uint2*)&sKh[bidx];
                const uint2 bvl = *(const uint2*)&sKl[bidx];
                bH[0] = bvh.x; bH[1] = bvh.y;
                bL[0] = bvl.x; bL[1] = bvl.y;
                mma_tf32(s[nf], aL, bH);
                mma_tf32(s[nf], aH, bL);
                mma_tf32(s[nf], aH, bH);
            }
        }

        // --- mask + online softmax (2 rows per lane: g and g+8) ---
#pragma unroll
        for (int rh = 0; rh < 2; rh++) {
            const int ig = m0 + w * 16 + g + rh * 8;
            float rmax = -1e30f;
#pragma unroll
            for (int nf = 0; nf < 8; nf++)
#pragma unroll
                for (int e = 0; e < 2; e++) {
                    int cl = nf * 8 + 2 * t + e;
                    int jg = n0 + cl;
                    float val = s[nf][rh * 2 + e] * 0.125f + sMask[cl];
                    if (jg > ig) val = -1e30f;
                    s[nf][rh * 2 + e] = val;
                    rmax = fmaxf(rmax, val);
                }
            rmax = fmaxf(rmax, __shfl_xor_sync(0xffffffffu, rmax, 1));
            rmax = fmaxf(rmax, __shfl_xor_sync(0xffffffffu, rmax, 2));
            float nm = fmaxf(m_i[rh], rmax);
            float corr = __expf(m_i[rh] - nm);
            m_i[rh] = nm;
            float rs = 0.f;
#pragma unroll
            for (int nf = 0; nf < 8; nf++)
#pragma unroll
                for (int e = 0; e < 2; e++) {
                    float p = __expf(s[nf][rh * 2 + e] - nm);
                    s[nf][rh * 2 + e] = p;
                    rs += p;
                }
            rs += __shfl_xor_sync(0xffffffffu, rs, 1);
            rs += __shfl_xor_sync(0xffffffffu, rs, 2);
            l_i[rh] = l_i[rh] * corr + rs;
#pragma unroll
            for (int nf = 0; nf < 8; nf++) {
                o[nf][rh * 2 + 0] *= corr;
                o[nf][rh * 2 + 1] *= corr;
            }
        }

        // --- stage P into per-warp A-fragment layout (ks' = nf) ---
#pragma unroll
        for (int nf = 0; nf < 8; nf++)
#pragma unroll
            for (int rh = 0; rh < 2; rh++)
#pragma unroll
                for (int e = 0; e < 2; e++) {
                    int c = 2 * t + e;                    // 0..7 within chunk
                    int ln = g * 4 + (c & 3);
                    int rg = rh + 2 * (c >> 2);
                    sP[((w * 8 + nf) * 32 + ln) * 4 + rg] = f2tf(s[nf][rh * 2 + e]);
                }
        __syncwarp();

        // --- O += P @ V (single tf32) ---
#pragma unroll
        for (int ks = 0; ks < 8; ks++) {
            unsigned a[4];
            const uint4 av = *(const uint4*)&sP[((w * 8 + ks) * 32 + lane) * 4];
            a[0] = av.x; a[1] = av.y; a[2] = av.z; a[3] = av.w;
#pragma unroll
            for (int nf = 0; nf < 8; nf++) {
                unsigned bfr[2];
                const uint2 bv = *(const uint2*)&sV[((nf * 8 + ks) * 32 + lane) * 2];
                bfr[0] = bv.x; bfr[1] = bv.y;
                mma_tf32(o[nf], a, bfr);
            }
        }
    }

    // --- normalize and store (B, S, NH, HD) ---
    float inv0 = 1.0f / l_i[0];
    float inv1 = 1.0f / l_i[1];
    int row0 = m0 + w * 16 + g;
#pragma unroll
    for (int nf = 0; nf < 8; nf++) {
        int col = nf * 8 + 2 * t;
        *(float2*)(out + (((size_t)b * CS + row0) * CNH + h) * CHD + col) =
            make_float2(o[nf][0] * inv0, o[nf][1] * inv0);
        *(float2*)(out + (((size_t)b * CS + row0 + 8) * CNH + h) * CHD + col) =
            make_float2(o[nf][2] * inv1, o[nf][3] * inv1);
    }
}

// ---------------------------------------------------------------------------
extern "C" void kernel_launch(void* const* d_in, const int* in_sizes, int n_in,
                              void* d_out, int out_size)
{
    const float* x     = (const float*)d_in[0];
    const float* cosp  = (const float*)d_in[1];
    const float* sinp  = (const float*)d_in[2];
    const float* amask = (const float*)d_in[3];
    const float* Wq    = (const float*)d_in[4];
    const float* Wk    = (const float*)d_in[5];
    const float* Wv    = (const float*)d_in[6];
    const float* Wo    = (const float*)d_in[7];
    float* out = (float*)d_out;

    float *qb, *kb, *vb, *ab;
    cudaGetSymbolAddress((void**)&qb, g_q);
    cudaGetSymbolAddress((void**)&kb, g_k);
    cudaGetSymbolAddress((void**)&vb, g_v);
    cudaGetSymbolAddress((void**)&ab, g_attn);

    // QKV projections (3xTF32 tensor cores, ~fp32 accurate)
    gemm_tf32_kernel<<<dim3(CNH * CHD / 128, CM / 128), 256>>>(CM, CNH * CHD, CH, x, Wq, qb);
    gemm_tf32_kernel<<<dim3(CNKV * CHD / 128, CM / 128), 256>>>(CM, CNKV * CHD, CH, x, Wk, kb);
    gemm_tf32_kernel<<<dim3(CNKV * CHD / 128, CM / 128), 256>>>(CM, CNKV * CHD, CH, x, Wv, vb);

    // RoPE on q and k
    {
        int nq = CB * CS * CNH * (CHD / 2);
        rope_kernel<<<(nq + 255) / 256, 256>>>(qb, cosp, sinp, CNH);
        int nk = CB * CS * CNKV * (CHD / 2);
        rope_kernel<<<(nk + 255) / 256, 256>>>(kb, cosp, sinp, CNKV);
    }

    // Attention (3xTF32 scores, tf32 PV, online softmax)
    cudaFuncSetAttribute(attn_mma_kernel, cudaFuncAttributeMaxDynamicSharedMemorySize,
                         ATT_SMEM_BYTES);
    attn_mma_kernel<<<dim3(CS / 128, CNH, CB), 256, ATT_SMEM_BYTES>>>(qb, kb, vb, amask, ab);

    // Output projection (3xTF32)
    gemm_tf32_kernel<<<dim3(CH / 128, CM / 128), 256>>>(CM, CH, CNH * CHD, ab, Wo, out);
}

// round 7
// speedup vs baseline: 1.3343x; 1.3343x over previous
#include <cuda_runtime.h>
#include <cuda_bf16.h>
#include <cstdint>

// Problem constants
constexpr int CB   = 2;
constexpr int CS   = 2048;
constexpr int CH   = 1024;
constexpr int CNH  = 16;
constexpr int CNKV = 4;
constexpr int CHD  = 64;
constexpr int CM   = CB * CS;        // 4096 rows

// Scratch (no cudaMalloc allowed)
__device__ float g_q[(size_t)CB * CS * CNH * CHD];     // 16 MB
__device__ float g_k[(size_t)CB * CS * CNKV * CHD];    // 4 MB
__device__ float g_v[(size_t)CB * CS * CNKV * CHD];    // 4 MB
__device__ float g_attn[(size_t)CB * CS * CNH * CHD];  // 16 MB

// ===========================================================================
// mma helpers (legacy mma.sync path — tcgen05 is not available because the
// harness emits PTX for target sm_103 without the 'a' feature suffix)
// ===========================================================================
__device__ __forceinline__ unsigned f2tf(float x) {
    unsigned u;
    asm("cvt.rna.tf32.f32 %0, %1;" : "=r"(u) : "f"(x));
    return u;
}

__device__ __forceinline__ void mma_tf32(float d[4], const unsigned a[4],
                                         const unsigned b[2]) {
    asm volatile(
        "mma.sync.aligned.m16n8k8.row.col.f32.tf32.tf32.f32 "
        "{%0,%1,%2,%3}, {%4,%5,%6,%7}, {%8,%9}, {%0,%1,%2,%3};"
        : "+f"(d[0]), "+f"(d[1]), "+f"(d[2]), "+f"(d[3])
        : "r"(a[0]), "r"(a[1]), "r"(a[2]), "r"(a[3]), "r"(b[0]), "r"(b[1]));
}

// bf16 m16n8k16: 2x MACs per instruction vs tf32 m16n8k8.
__device__ __forceinline__ void mma_bf16(float d[4], const unsigned a[4],
                                         const unsigned b[2]) {
    asm volatile(
        "mma.sync.aligned.m16n8k16.row.col.f32.bf16.bf16.f32 "
        "{%0,%1,%2,%3}, {%4,%5,%6,%7}, {%8,%9}, {%0,%1,%2,%3};"
        : "+f"(d[0]), "+f"(d[1]), "+f"(d[2]), "+f"(d[3])
        : "r"(a[0]), "r"(a[1]), "r"(a[2]), "r"(a[3]), "r"(b[0]), "r"(b[1]));
}

// bf16 hi/lo split of a k-consecutive pair (x = even k -> low half).
__device__ __forceinline__ void pack_split(float x, float y,
                                           uint32_t& hi, uint32_t& lo) {
    __nv_bfloat16 hx = __float2bfloat16(x), hy = __float2bfloat16(y);
    float rx = x - __bfloat162float(hx);
    float ry = y - __bfloat162float(hy);
    __nv_bfloat16 lx = __float2bfloat16(rx), ly = __float2bfloat16(ry);
    hi = (uint32_t)__bfloat16_as_ushort(hx) | ((uint32_t)__bfloat16_as_ushort(hy) << 16);
    lo = (uint32_t)__bfloat16_as_ushort(lx) | ((uint32_t)__bfloat16_as_ushort(ly) << 16);
}

// ===========================================================================
// GEMM via bf16-split mma (3 terms: AH*BH + AH*BL + AL*BH), fp32 acc.
// C = A(MxK) @ B(KxN), row-major fp32. Block 128x128, BK=16, 256 thr, 8 warps
// (2x4), warp tile 64x32 (4x4 of m16n8k16 fragments).
// ===========================================================================
__global__ __launch_bounds__(256) void gemm_bf16_kernel(
    int M, int N, int K,
    const float* __restrict__ A, const float* __restrict__ Bm,
    float* __restrict__ C)
{
    // sA*: [mfb(8)][lane(32)][reg(4)]  sB*: [nfb(16)][lane(32)][reg(2)]
    __shared__ uint32_t sAh[1024], sAl[1024];
    __shared__ uint32_t sBh[1024], sBl[1024];

    const int tid  = threadIdx.x;
    const int lane = tid & 31;
    const int w    = tid >> 5;
    const int wm   = w >> 2;          // 0..1
    const int wn   = w & 3;           // 0..3
    const int g    = lane >> 2;       // 0..7
    const int t    = lane & 3;        // 0..3
    const int brow = blockIdx.y, bcol = blockIdx.x;

    A  += (size_t)brow * 128 * K;
    Bm += (size_t)bcol * 128;
    C  += (size_t)brow * 128 * N + (size_t)bcol * 128;

    float acc[4][4][4];
#pragma unroll
    for (int i = 0; i < 4; i++)
#pragma unroll
        for (int j = 0; j < 4; j++)
#pragma unroll
            for (int r = 0; r < 4; r++) acc[i][j][r] = 0.f;

    const int aRow = tid >> 1;             // 0..127
    const int aK0  = (tid & 1) * 8;        // 0 or 8
    const int bKp  = tid >> 5;             // 0..7 (k-pair index)
    const int bC0  = (tid & 31) * 4;       // 0..124

    for (int k0 = 0; k0 < K; k0 += 16) {
        __syncthreads();
        // --- stage A (128x16) as bf16 hi/lo fragments ---
        const int mfb = aRow >> 4, rr = aRow & 15;
#pragma unroll
        for (int h4 = 0; h4 < 2; h4++) {
            float4 a4 = *(const float4*)(A + (size_t)aRow * K + k0 + aK0 + h4 * 4);
            float av[4] = {a4.x, a4.y, a4.z, a4.w};
#pragma unroll
            for (int p = 0; p < 2; p++) {
                int kk = aK0 + h4 * 4 + 2 * p;
                uint32_t hi, lo;
                pack_split(av[2 * p], av[2 * p + 1], hi, lo);
                int reg = (rr >> 3) + 2 * (kk >> 3);
                int ln  = (rr & 7) * 4 + ((kk & 7) >> 1);
                int idx = (mfb * 32 + ln) * 4 + reg;
                sAh[idx] = hi;
                sAl[idx] = lo;
            }
        }
        // --- stage B (16x128) as bf16 hi/lo fragments (pairs along k) ---
        {
            float4 b0 = *(const float4*)(Bm + (size_t)(k0 + 2 * bKp) * N + bC0);
            float4 b1 = *(const float4*)(Bm + (size_t)(k0 + 2 * bKp + 1) * N + bC0);
            float e0[4] = {b0.x, b0.y, b0.z, b0.w};
            float e1[4] = {b1.x, b1.y, b1.z, b1.w};
            int kk = 2 * bKp;
#pragma unroll
            for (int j = 0; j < 4; j++) {
                uint32_t hi, lo;
                pack_split(e0[j], e1[j], hi, lo);
                int cc  = bC0 + j;
                int nfb = cc >> 3;
                int reg = kk >> 3;
                int ln  = (cc & 7) * 4 + ((kk & 7) >> 1);
                int idx = (nfb * 32 + ln) * 2 + reg;
                sBh[idx] = hi;
                sBl[idx] = lo;
            }
        }
        __syncthreads();

        // --- compute: 3-term bf16-split ---
        unsigned aH[4][4], aL[4][4];
        unsigned bH[4][2], bL[4][2];
#pragma unroll
        for (int mf = 0; mf < 4; mf++) {
            int idx = ((wm * 4 + mf) * 32 + lane) * 4;
            uint4 vh = *(const uint4*)&sAh[idx];
            uint4 vl = *(const uint4*)&sAl[idx];
            aH[mf][0] = vh.x; aH[mf][1] = vh.y; aH[mf][2] = vh.z; aH[mf][3] = vh.w;
            aL[mf][0] = vl.x; aL[mf][1] = vl.y; aL[mf][2] = vl.z; aL[mf][3] = vl.w;
        }
#pragma unroll
        for (int nf = 0; nf < 4; nf++) {
            int idx = ((wn * 4 + nf) * 32 + lane) * 2;
            uint2 vh = *(const uint2*)&sBh[idx];
            uint2 vl = *(const uint2*)&sBl[idx];
            bH[nf][0] = vh.x; bH[nf][1] = vh.y;
            bL[nf][0] = vl.x; bL[nf][1] = vl.y;
        }
#pragma unroll
        for (int mf = 0; mf < 4; mf++)
#pragma unroll
            for (int nf = 0; nf < 4; nf++) {
                mma_bf16(acc[mf][nf], aL[mf], bH[nf]);
                mma_bf16(acc[mf][nf], aH[mf], bL[nf]);
                mma_bf16(acc[mf][nf], aH[mf], bH[nf]);
            }
    }

    // --- epilogue ---
#pragma unroll
    for (int mf = 0; mf < 4; mf++) {
        int row0 = wm * 64 + mf * 16 + g;
#pragma unroll
        for (int nf = 0; nf < 4; nf++) {
            int col = wn * 32 + nf * 8 + 2 * t;
            *(float2*)(C + (size_t)row0 * N + col) =
                make_float2(acc[mf][nf][0], acc[mf][nf][1]);
            *(float2*)(C + (size_t)(row0 + 8) * N + col) =
                make_float2(acc[mf][nf][2], acc[mf][nf][3]);
        }
    }
}

// ---------------------------------------------------------------------------
// RoPE (half-rotation). Each thread handles a (d, d+32) pair -> race-free.
// ---------------------------------------------------------------------------
__global__ void rope_kernel(float* __restrict__ x, const float* __restrict__ cosp,
                            const float* __restrict__ sinp, int nheads)
{
    int idx = blockIdx.x * blockDim.x + threadIdx.x;
    int total = CB * CS * nheads * (CHD / 2);
    if (idx >= total) return;
    int d = idx & 31;
    int tt = idx >> 5;
    int s = (tt / nheads) % CS;
    float* p = x + (size_t)tt * CHD;
    float x0 = p[d];
    float x1 = p[d + 32];
    float c0 = cosp[s * CHD + d],      s0 = sinp[s * CHD + d];
    float c1 = cosp[s * CHD + d + 32], s1 = sinp[s * CHD + d + 32];
    p[d]      = x0 * c0 - x1 * s0;
    p[d + 32] = x1 * c1 + x0 * s1;
}

// ---------------------------------------------------------------------------
// Flash attention. S = Q@K^T via bf16-split m16n8k16 (3 terms),
// O += P@V via single tf32 m16n8k8 (unchanged, error-budgeted).
// Q tile 128 rows, KV tile 64; 8 warps, warp w owns q rows [w*16, w*16+16).
// smem (u32): sQh 4096 | sQl 4096 | sKh 2048 | sKl 2048 | sV 4096 | sP 8192
//             | mask 64 = 24640 floats = 98,560 B
// ---------------------------------------------------------------------------
constexpr int ATT_SMEM_FLOATS = 4096 + 4096 + 2048 + 2048 + 4096 + 8192 + 64;
constexpr int ATT_SMEM_BYTES  = ATT_SMEM_FLOATS * 4;

__global__ __launch_bounds__(256) void attn_mma_kernel(
    const float* __restrict__ q, const float* __restrict__ k,
    const float* __restrict__ v, const float* __restrict__ amask,
    float* __restrict__ out)
{
    extern __shared__ float smf[];
    uint32_t* sQh = (uint32_t*)smf;                  // 4096
    uint32_t* sQl = (uint32_t*)(smf + 4096);         // 4096
    uint32_t* sKh = (uint32_t*)(smf + 8192);         // 2048
    uint32_t* sKl = (uint32_t*)(smf + 10240);        // 2048
    uint32_t* sV  = (uint32_t*)(smf + 12288);        // 4096
    uint32_t* sP  = (uint32_t*)(smf + 16384);        // 8192
    float*    sMask = smf + 24576;                   // 64

    const int tid  = threadIdx.x;
    const int lane = tid & 31;
    const int w    = tid >> 5;
    const int g    = lane >> 2;
    const int t    = lane & 3;
    const int mt = blockIdx.x, h = blockIdx.y, b = blockIdx.z;
    const int grp = h >> 2;           // NKV group (R = 4)
    const int m0 = mt * 128;

    // --- stage Q tile (128 x 64) into per-warp bf16 A-fragment layout ---
    // sQ*: [wq(8)][ks(4)][lane(32)][reg(4)]
#pragma unroll
    for (int i = 0; i < 8; i++) {
        int idx = tid + i * 256;
        int r = idx >> 4, k4 = (idx & 15) * 4;
        float4 qv = *(const float4*)(
            q + (((size_t)b * CS + m0 + r) * CNH + h) * CHD + k4);
        float qa[4] = {qv.x, qv.y, qv.z, qv.w};
        int wq = r >> 4, rr = r & 15;
#pragma unroll
        for (int p = 0; p < 2; p++) {
            int kk = k4 + 2 * p;
            int ks = kk >> 4, kloc = kk & 15;
            uint32_t hi, lo;
            pack_split(qa[2 * p], qa[2 * p + 1], hi, lo);
            int reg = (rr >> 3) + 2 * (kloc >> 3);
            int ln  = (rr & 7) * 4 + ((kloc & 7) >> 1);
            int sidx = ((wq * 4 + ks) * 32 + ln) * 4 + reg;
            sQh[sidx] = hi;
            sQl[sidx] = lo;
        }
    }

    float o[8][4];
    float m_i[2] = {-1e30f, -1e30f};
    float l_i[2] = {0.f, 0.f};
#pragma unroll
    for (int nf = 0; nf < 8; nf++)
#pragma unroll
        for (int r = 0; r < 4; r++) o[nf][r] = 0.f;

    const int ntmax = 2 * mt + 1;
    for (int nt = 0; nt <= ntmax; nt++) {
        const int n0 = nt * 64;
        __syncthreads();
        // --- stage K (bf16 hi/lo B-frag) and V (tf32 B-frag) ---
        // sK*: [nfb(8)][ks(4)][lane(32)][reg(2)]
#pragma unroll
        for (int i = 0; i < 4; i++) {
            int idx = tid + i * 256;
            int r = idx >> 4, k4 = (idx & 15) * 4;
            size_t gbase = (((size_t)b * CS + n0 + r) * CNKV + grp) * CHD + k4;
            float4 kv4 = *(const float4*)(k + gbase);
            float4 vv4 = *(const float4*)(v + gbase);
            float ka[4] = {kv4.x, kv4.y, kv4.z, kv4.w};
            float va[4] = {vv4.x, vv4.y, vv4.z, vv4.w};
            int nfb = r >> 3, cc = r & 7;
#pragma unroll
            for (int p = 0; p < 2; p++) {
                int kk = k4 + 2 * p;
                int ks = kk >> 4, kloc = kk & 15;
                uint32_t hi, lo;
                pack_split(ka[2 * p], ka[2 * p + 1], hi, lo);
                int reg = kloc >> 3;
                int ln  = cc * 4 + ((kloc & 7) >> 1);
                int kidx = ((nfb * 4 + ks) * 32 + ln) * 2 + reg;
                sKh[kidx] = hi;
                sKl[kidx] = lo;
            }
#pragma unroll
            for (int e = 0; e < 4; e++) {
                int kk = k4 + e;
                // V element (k = r, n = kk), tf32 B-frag [nfb(8)][ks(8)][lane][2]
                sV[(((kk >> 3) * 8 + (r >> 3)) * 32 + (kk & 7) * 4 + (r & 3)) * 2 +
                   ((r & 7) >> 2)] = f2tf(va[e]);
            }
        }
        if (tid < 64)
            sMask[tid] = (1.0f - amask[(size_t)b * CS + n0 + tid]) * -1e9f;
        __syncthreads();

        // --- S = Q @ K^T (bf16-split, 3 terms): per warp 16 x 64 ---
        float s[8][4];
#pragma unroll
        for (int nf = 0; nf < 8; nf++)
#pragma unroll
            for (int r = 0; r < 4; r++) s[nf][r] = 0.f;

#pragma unroll
        for (int ks = 0; ks < 4; ks++) {
            unsigned aH[4], aL[4];
            int aidx = ((w * 4 + ks) * 32 + lane) * 4;
            const uint4 avh = *(const uint4*)&sQh[aidx];
            const uint4 avl = *(const uint4*)&sQl[aidx];
            aH[0] = avh.x; aH[1] = avh.y; aH[2] = avh.z; aH[3] = avh.w;
            aL[0] = avl.x; aL[1] = avl.y; aL[2] = avl.z; aL[3] = avl.w;
#pragma unroll
            for (int nf = 0; nf < 8; nf++) {
                unsigned bH[2], bL[2];
                int bidx = ((nf * 4 + ks) * 32 + lane) * 2;
                const uint2 bvh = *(const uint2*)&sKh[bidx];
                const uint2 bvl = *(const uint2*)&sKl[bidx];
                bH[0] = bvh.x; bH[1] = bvh.y;
                bL[0] = bvl.x; bL[1] = bvl.y;
                mma_bf16(s[nf], aL, bH);
                mma_bf16(s[nf], aH, bL);
                mma_bf16(s[nf], aH, bH);
            }
        }

        // --- mask + online softmax (2 rows per lane: g and g+8) ---
#pragma unroll
        for (int rh = 0; rh < 2; rh++) {
            const int ig = m0 + w * 16 + g + rh * 8;
            float rmax = -1e30f;
#pragma unroll
            for (int nf = 0; nf < 8; nf++)
#pragma unroll
                for (int e = 0; e < 2; e++) {
                    int cl = nf * 8 + 2 * t + e;
                    int jg = n0 + cl;
                    float val = s[nf][rh * 2 + e] * 0.125f + sMask[cl];
                    if (jg > ig) val = -1e30f;
                    s[nf][rh * 2 + e] = val;
                    rmax = fmaxf(rmax, val);
                }
            rmax = fmaxf(rmax, __shfl_xor_sync(0xffffffffu, rmax, 1));
            rmax = fmaxf(rmax, __shfl_xor_sync(0xffffffffu, rmax, 2));
            float nm = fmaxf(m_i[rh], rmax);
            float corr = __expf(m_i[rh] - nm);
            m_i[rh] = nm;
            float rs = 0.f;
#pragma unroll
            for (int nf = 0; nf < 8; nf++)
#pragma unroll
                for (int e = 0; e < 2; e++) {
                    float p = __expf(s[nf][rh * 2 + e] - nm);
                    s[nf][rh * 2 + e] = p;
                    rs += p;
                }
            rs += __shfl_xor_sync(0xffffffffu, rs, 1);
            rs += __shfl_xor_sync(0xffffffffu, rs, 2);
            l_i[rh] = l_i[rh] * corr + rs;
#pragma unroll
            for (int nf = 0; nf < 8; nf++) {
                o[nf][rh * 2 + 0] *= corr;
                o[nf][rh * 2 + 1] *= corr;
            }
        }

        // --- stage P into per-warp tf32 A-fragment layout (ks' = nf) ---
#pragma unroll
        for (int nf = 0; nf < 8; nf++)
#pragma unroll
            for (int rh = 0; rh < 2; rh++)
#pragma unroll
                for (int e = 0; e < 2; e++) {
                    int c = 2 * t + e;
                    int ln = g * 4 + (c & 3);
                    int rg = rh + 2 * (c >> 2);
                    sP[((w * 8 + nf) * 32 + ln) * 4 + rg] = f2tf(s[nf][rh * 2 + e]);
                }
        __syncwarp();

        // --- O += P @ V (single tf32) ---
#pragma unroll
        for (int ks = 0; ks < 8; ks++) {
            unsigned a[4];
            const uint4 av = *(const uint4*)&sP[((w * 8 + ks) * 32 + lane) * 4];
            a[0] = av.x; a[1] = av.y; a[2] = av.z; a[3] = av.w;
#pragma unroll
            for (int nf = 0; nf < 8; nf++) {
                unsigned bfr[2];
                const uint2 bv = *(const uint2*)&sV[((nf * 8 + ks) * 32 + lane) * 2];
                bfr[0] = bv.x; bfr[1] = bv.y;
                mma_tf32(o[nf], a, bfr);
            }
        }
    }

    // --- normalize and store (B, S, NH, HD) ---
    float inv0 = 1.0f / l_i[0];
    float inv1 = 1.0f / l_i[1];
    int row0 = m0 + w * 16 + g;
#pragma unroll
    for (int nf = 0; nf < 8; nf++) {
        int col = nf * 8 + 2 * t;
        *(float2*)(out + (((size_t)b * CS + row0) * CNH + h) * CHD + col) =
            make_float2(o[nf][0] * inv0, o[nf][1] * inv0);
        *(float2*)(out + (((size_t)b * CS + row0 + 8) * CNH + h) * CHD + col) =
            make_float2(o[nf][2] * inv1, o[nf][3] * inv1);
    }
}

// ---------------------------------------------------------------------------
extern "C" void kernel_launch(void* const* d_in, const int* in_sizes, int n_in,
                              void* d_out, int out_size)
{
    const float* x     = (const float*)d_in[0];
    const float* cosp  = (const float*)d_in[1];
    const float* sinp  = (const float*)d_in[2];
    const float* amask = (const float*)d_in[3];
    const float* Wq    = (const float*)d_in[4];
    const float* Wk    = (const float*)d_in[5];
    const float* Wv    = (const float*)d_in[6];
    const float* Wo    = (const float*)d_in[7];
    float* out = (float*)d_out;

    float *qb, *kb, *vb, *ab;
    cudaGetSymbolAddress((void**)&qb, g_q);
    cudaGetSymbolAddress((void**)&kb, g_k);
    cudaGetSymbolAddress((void**)&vb, g_v);
    cudaGetSymbolAddress((void**)&ab, g_attn);

    cudaFuncSetAttribute(attn_mma_kernel, cudaFuncAttributeMaxDynamicSharedMemorySize,
                         ATT_SMEM_BYTES);

    // QKV projections (bf16-split, 3-term, fp32 accum)
    gemm_bf16_kernel<<<dim3(CNH * CHD / 128, CM / 128), 256>>>(CM, CNH * CHD, CH, x, Wq, qb);
    gemm_bf16_kernel<<<dim3(CNKV * CHD / 128, CM / 128), 256>>>(CM, CNKV * CHD, CH, x, Wk, kb);
    gemm_bf16_kernel<<<dim3(CNKV * CHD / 128, CM / 128), 256>>>(CM, CNKV * CHD, CH, x, Wv, vb);

    // RoPE on q and k
    {
        int nq = CB * CS * CNH * (CHD / 2);
        rope_kernel<<<(nq + 255) / 256, 256>>>(qb, cosp, sinp, CNH);
        int nk = CB * CS * CNKV * (CHD / 2);
        rope_kernel<<<(nk + 255) / 256, 256>>>(kb, cosp, sinp, CNKV);
    }

    // Attention (bf16-split scores, tf32 PV, online softmax)
    attn_mma_kernel<<<dim3(CS / 128, CNH, CB), 256, ATT_SMEM_BYTES>>>(qb, kb, vb, amask, ab);

    // Output projection (bf16-split)
    gemm_bf16_kernel<<<dim3(CH / 128, CM / 128), 256>>>(CM, CH, CNH * CHD, ab, Wo, out);
}

// round 9
// speedup vs baseline: 2.8697x; 2.1508x over previous
#include <cuda_runtime.h>
#include <cuda_bf16.h>
#include <cstdint>

// Problem constants
constexpr int CB   = 2;
constexpr int CS   = 2048;
constexpr int CH   = 1024;
constexpr int CNH  = 16;
constexpr int CNKV = 4;
constexpr int CHD  = 64;
constexpr int CM   = CB * CS;          // 4096 rows
constexpr int NQKV = CNH * CHD + 2 * CNKV * CHD;  // 1536
constexpr int KOFF = CNH * CHD;        // 1024 (k starts here in qkv)
constexpr int VOFF = KOFF + CNKV * CHD; // 1280

// ---------------------------------------------------------------------------
// Scratch (no cudaMalloc allowed)
// ---------------------------------------------------------------------------
__device__ uint32_t g_xh[(size_t)CM * CH / 2];          // x A-frag hi
__device__ uint32_t g_xl[(size_t)CM * CH / 2];          // x A-frag lo
__device__ uint32_t g_wh[(size_t)CH * NQKV / 2];        // Wqkv B-frag hi
__device__ uint32_t g_wl[(size_t)CH * NQKV / 2];
__device__ uint32_t g_woh[(size_t)CH * CH / 2];         // Wo B-frag hi
__device__ uint32_t g_wol[(size_t)CH * CH / 2];
__device__ float    g_qkv[(size_t)CM * NQKV];           // fused QKV output
__device__ uint32_t g_qfh[(size_t)CB * CNH * CS * CHD / 2];   // roped q A-frag
__device__ uint32_t g_qfl[(size_t)CB * CNH * CS * CHD / 2];
__device__ uint32_t g_kfh[(size_t)CB * CNKV * CS * CHD / 2];  // roped k B-frag
__device__ uint32_t g_kfl[(size_t)CB * CNKV * CS * CHD / 2];
__device__ uint32_t g_vf[(size_t)CB * CNKV * CS * CHD];       // v tf32 B-frag
__device__ float    g_bias[(size_t)CB * CS];
__device__ float    g_attn[(size_t)CM * CNH * CHD];     // attention out (row-major)
__device__ uint32_t g_ah[(size_t)CM * CH / 2];          // attn out A-frag hi
__device__ uint32_t g_al[(size_t)CM * CH / 2];

// ---------------------------------------------------------------------------
// mma helpers (legacy mma.sync path — tcgen05 unavailable: harness targets sm_103)
// ---------------------------------------------------------------------------
__device__ __forceinline__ unsigned f2tf(float x) {
    unsigned u;
    asm("cvt.rna.tf32.f32 %0, %1;" : "=r"(u) : "f"(x));
    return u;
}

__device__ __forceinline__ void mma_bf16(float d[4], const uint4& a, const uint2& b) {
    asm volatile(
        "mma.sync.aligned.m16n8k16.row.col.f32.bf16.bf16.f32 "
        "{%0,%1,%2,%3}, {%4,%5,%6,%7}, {%8,%9}, {%0,%1,%2,%3};"
        : "+f"(d[0]), "+f"(d[1]), "+f"(d[2]), "+f"(d[3])
        : "r"(a.x), "r"(a.y), "r"(a.z), "r"(a.w), "r"(b.x), "r"(b.y));
}

__device__ __forceinline__ void mma_tf32(float d[4], const uint4& a, const uint2& b) {
    asm volatile(
        "mma.sync.aligned.m16n8k8.row.col.f32.tf32.tf32.f32 "
        "{%0,%1,%2,%3}, {%4,%5,%6,%7}, {%8,%9}, {%0,%1,%2,%3};"
        : "+f"(d[0]), "+f"(d[1]), "+f"(d[2]), "+f"(d[3])
        : "r"(a.x), "r"(a.y), "r"(a.z), "r"(a.w), "r"(b.x), "r"(b.y));
}

// bf16 hi/lo split of a k-consecutive pair (x = even k -> low half).
__device__ __forceinline__ void pack_split(float x, float y,
                                           uint32_t& hi, uint32_t& lo) {
    __nv_bfloat16 hx = __float2bfloat16(x), hy = __float2bfloat16(y);
    float rx = x - __bfloat162float(hx);
    float ry = y - __bfloat162float(hy);
    __nv_bfloat16 lx = __float2bfloat16(rx), ly = __float2bfloat16(ry);
    hi = (uint32_t)__bfloat16_as_ushort(hx) | ((uint32_t)__bfloat16_as_ushort(hy) << 16);
    lo = (uint32_t)__bfloat16_as_ushort(lx) | ((uint32_t)__bfloat16_as_ushort(ly) << 16);
}

// ---------------------------------------------------------------------------
// split_a: fp32 row-major A[M][K] -> bf16 hi/lo in m16k16 A-fragment order.
// frag addr = ((fb*(K/16)+ks)*32 + ln)*4 + reg
// ---------------------------------------------------------------------------
__global__ void split_a_kernel(const float* __restrict__ A,
                               uint32_t* __restrict__ Oh, uint32_t* __restrict__ Ol,
                               int M, int K)
{
    int idx = blockIdx.x * blockDim.x + threadIdx.x;
    int total = M * (K / 2);
    if (idx >= total) return;
    int row = idx / (K / 2);
    int kp  = idx - row * (K / 2);
    float2 v = *(const float2*)(A + (size_t)row * K + 2 * kp);
    uint32_t hi, lo;
    pack_split(v.x, v.y, hi, lo);
    int kk = 2 * kp, fb = row >> 4, rr = row & 15, ks = kk >> 4, kloc = kk & 15;
    int reg = (rr >> 3) + 2 * (kloc >> 3);
    int ln  = (rr & 7) * 4 + ((kloc & 7) >> 1);
    size_t o = (((size_t)fb * (K / 16) + ks) * 32 + ln) * 4 + reg;
    Oh[o] = hi;
    Ol[o] = lo;
}

// ---------------------------------------------------------------------------
// split_b: fp32 row-major W[K][N] -> bf16 hi/lo in n8k16 B-fragment order,
// placed at column offset col_off in the combined output array.
// frag addr = ((nb*(K/16)+ks)*32 + ln)*2 + reg
// ---------------------------------------------------------------------------
__global__ void split_b_kernel(const float* __restrict__ W,
                               uint32_t* __restrict__ Oh, uint32_t* __restrict__ Ol,
                               int K, int N, int col_off)
{
    int idx = blockIdx.x * blockDim.x + threadIdx.x;
    int total = (K / 2) * N;
    if (idx >= total) return;
    int kp  = idx / N;
    int col = idx - kp * N;
    float a = W[(size_t)(2 * kp) * N + col];
    float b = W[(size_t)(2 * kp + 1) * N + col];
    uint32_t hi, lo;
    pack_split(a, b, hi, lo);
    int kk = 2 * kp, cg = col_off + col, nb = cg >> 3, cc = cg & 7;
    int ks = kk >> 4, kloc = kk & 15;
    int reg = kloc >> 3;
    int ln  = cc * 4 + ((kloc & 7) >> 1);
    size_t o = (((size_t)nb * (K / 16) + ks) * 32 + ln) * 2 + reg;
    Oh[o] = hi;
    Ol[o] = lo;
}

// ---------------------------------------------------------------------------
// GEMM (K=1024 hard-coded): C = A @ B, 3-term bf16-split, fragments loaded
// directly from global in fragment order. No smem, no syncs.
// Block 128x128, 8 warps (2x4), warp tile 64x32.
// ---------------------------------------------------------------------------
constexpr int GKS = CH / 16;  // 64

__global__ __launch_bounds__(256) void gemm_frag_kernel(
    int M, int N,
    const uint32_t* __restrict__ Ah, const uint32_t* __restrict__ Al,
    const uint32_t* __restrict__ Bh, const uint32_t* __restrict__ Bl,
    float* __restrict__ C)
{
    const int tid  = threadIdx.x;
    const int lane = tid & 31;
    const int w    = tid >> 5;
    const int wm   = w >> 2;
    const int wn   = w & 3;
    const int g    = lane >> 2;
    const int t    = lane & 3;

    float acc[4][4][4];
#pragma unroll
    for (int i = 0; i < 4; i++)
#pragma unroll
        for (int j = 0; j < 4; j++)
#pragma unroll
            for (int r = 0; r < 4; r++) acc[i][j][r] = 0.f;

    // mf fragment stride = GKS*128 u32 ; nf fragment stride = GKS*64 u32
    const uint32_t* pAh = Ah + ((size_t)(blockIdx.y * 8 + wm * 4) * GKS * 32 + lane) * 4;
    const uint32_t* pAl = Al + ((size_t)(blockIdx.y * 8 + wm * 4) * GKS * 32 + lane) * 4;
    const uint32_t* pBh = Bh + ((size_t)(blockIdx.x * 16 + wn * 4) * GKS * 32 + lane) * 2;
    const uint32_t* pBl = Bl + ((size_t)(blockIdx.x * 16 + wn * 4) * GKS * 32 + lane) * 2;

#pragma unroll 2
    for (int ks = 0; ks < GKS; ks++) {
        uint4 ah[4], al[4];
        uint2 bh[4], bl[4];
#pragma unroll
        for (int mf = 0; mf < 4; mf++) {
            ah[mf] = *(const uint4*)(pAh + (size_t)mf * GKS * 128);
            al[mf] = *(const uint4*)(pAl + (size_t)mf * GKS * 128);
        }
#pragma unroll
        for (int nf = 0; nf < 4; nf++) {
            bh[nf] = *(const uint2*)(pBh + (size_t)nf * GKS * 64);
            bl[nf] = *(const uint2*)(pBl + (size_t)nf * GKS * 64);
        }
#pragma unroll
        for (int mf = 0; mf < 4; mf++)
#pragma unroll
            for (int nf = 0; nf < 4; nf++) {
                mma_bf16(acc[mf][nf], al[mf], bh[nf]);
                mma_bf16(acc[mf][nf], ah[mf], bl[nf]);
                mma_bf16(acc[mf][nf], ah[mf], bh[nf]);
            }
        pAh += 128; pAl += 128; pBh += 64; pBl += 64;
    }

    float* Cp = C + (size_t)blockIdx.y * 128 * N + blockIdx.x * 128;
#pragma unroll
    for (int mf = 0; mf < 4; mf++) {
        int row0 = wm * 64 + mf * 16 + g;
#pragma unroll
        for (int nf = 0; nf < 4; nf++) {
            int col = wn * 32 + nf * 8 + 2 * t;
            *(float2*)(Cp + (size_t)row0 * N + col) =
                make_float2(acc[mf][nf][0], acc[mf][nf][1]);
            *(float2*)(Cp + (size_t)(row0 + 8) * N + col) =
                make_float2(acc[mf][nf][2], acc[mf][nf][3]);
        }
    }
}

// ---------------------------------------------------------------------------
// RoPE + split for Q: read fused qkv fp32, rotate, write bf16 hi/lo A-frags.
// Each thread: (b, s, h, dpair) handles d, d+1, d+32, d+33.
// Q-frag addr per (b,h): (((fb)*4 + ks)*32 + ln)*4 + reg, fb = s>>4.
// ---------------------------------------------------------------------------
__global__ void rope_split_q_kernel(const float* __restrict__ qkv,
                                    const float* __restrict__ cosp,
                                    const float* __restrict__ sinp,
                                    uint32_t* __restrict__ Qh, uint32_t* __restrict__ Ql)
{
    int idx = blockIdx.x * blockDim.x + threadIdx.x;
    if (idx >= CB * CS * CNH * 16) return;
    int dp = idx & 15;
    int t2 = idx >> 4;
    int h = t2 % CNH;
    int t3 = t2 / CNH;
    int s = t3 % CS;
    int b = t3 / CS;
    int d = 2 * dp;
    const float* p = qkv + (size_t)(b * CS + s) * NQKV + h * CHD;
    float x0 = p[d], x1 = p[d + 1], y0 = p[d + 32], y1 = p[d + 33];
    const float* cr = cosp + s * CHD;
    const float* sr = sinp + s * CHD;
    float r0 = x0 * cr[d]      - y0 * sr[d];
    float r1 = x1 * cr[d + 1]  - y1 * sr[d + 1];
    float rA = y0 * cr[d + 32] + x0 * sr[d + 32];
    float rB = y1 * cr[d + 33] + x1 * sr[d + 33];

    int fb = s >> 4, rr = s & 15;
    size_t base = ((size_t)(b * CNH + h) * (CS / 16) + fb) * 4;
#pragma unroll
    for (int half = 0; half < 2; half++) {
        int kk = d + half * 32;
        uint32_t hi, lo;
        if (half == 0) pack_split(r0, r1, hi, lo);
        else           pack_split(rA, rB, hi, lo);
        int ks = kk >> 4, kloc = kk & 15;
        int reg = (rr >> 3) + 2 * (kloc >> 3);
        int ln  = (rr & 7) * 4 + ((kloc & 7) >> 1);
        size_t o = ((base + ks) * 32 + ln) * 4 + reg;
        Qh[o] = hi;
        Ql[o] = lo;
    }
}

// ---------------------------------------------------------------------------
// RoPE + split for K: write n8k16 B-frags (n = kv pos, k = d).
// K-frag addr per (b,g): ((nfb*4 + ks)*32 + ln)*2 + reg, nfb = s>>3.
// ---------------------------------------------------------------------------
__global__ void rope_split_k_kernel(const float* __restrict__ qkv,
                                    const float* __restrict__ cosp,
                                    const float* __restrict__ sinp,
                                    uint32_t* __restrict__ Kh, uint32_t* __restrict__ Kl)
{
    int idx = blockIdx.x * blockDim.x + threadIdx.x;
    if (idx >= CB * CS * CNKV * 16) return;
    int dp = idx & 15;
    int t2 = idx >> 4;
    int h = t2 % CNKV;
    int t3 = t2 / CNKV;
    int s = t3 % CS;
    int b = t3 / CS;
    int d = 2 * dp;
    const float* p = qkv + (size_t)(b * CS + s) * NQKV + KOFF + h * CHD;
    float x0 = p[d], x1 = p[d + 1], y0 = p[d + 32], y1 = p[d + 33];
    const float* cr = cosp + s * CHD;
    const float* sr = sinp + s * CHD;
    float r0 = x0 * cr[d]      - y0 * sr[d];
    float r1 = x1 * cr[d + 1]  - y1 * sr[d + 1];
    float rA = y0 * cr[d + 32] + x0 * sr[d + 32];
    float rB = y1 * cr[d + 33] + x1 * sr[d + 33];

    int nfb = s >> 3, cc = s & 7;
    size_t base = ((size_t)(b * CNKV + h) * (CS / 8) + nfb) * 4;
#pragma unroll
    for (int half = 0; half < 2; half++) {
        int kk = d + half * 32;
        uint32_t hi, lo;
        if (half == 0) pack_split(r0, r1, hi, lo);
        else           pack_split(rA, rB, hi, lo);
        int ks = kk >> 4, kloc = kk & 15;
        int reg = kloc >> 3;
        int ln  = cc * 4 + ((kloc & 7) >> 1);
        size_t o = ((base + ks) * 32 + ln) * 2 + reg;
        Kh[o] = hi;
        Kl[o] = lo;
    }
}

// ---------------------------------------------------------------------------
// V -> tf32 n8k8 B-frag (n = d, k = kv pos) + bias precompute.
// V-frag addr per (b,g): ((kb*8 + nfb)*32 + ln)*2 + reg, kb = s>>3.
// ---------------------------------------------------------------------------
__global__ void conv_v_kernel(const float* __restrict__ qkv,
                              const float* __restrict__ amask,
                              uint32_t* __restrict__ Vf, float* __restrict__ bias)
{
    int idx = blockIdx.x * blockDim.x + threadIdx.x;
    if (idx < CB * CS) bias[idx] = (1.0f - amask[idx]) * -1e9f;
    if (idx >= CB * CS * CNKV * CHD) return;
    int d = idx & 63;
    int t2 = idx >> 6;
    int h = t2 % CNKV;
    int t3 = t2 / CNKV;
    int s = t3 % CS;
    int b = t3 / CS;
    float val = qkv[(size_t)(b * CS + s) * NQKV + VOFF + h * CHD + d];
    int kb = s >> 3, sl = s & 7, nfb = d >> 3, dc = d & 7;
    int ln = dc * 4 + (sl & 3);
    int reg = sl >> 2;
    size_t o = (((size_t)(b * CNKV + h) * (CS / 8) + kb) * 8 + nfb) * 32;
    Vf[(o + ln) * 2 + reg] = f2tf(val);
}

// ---------------------------------------------------------------------------
// Flash attention: Q frags in registers, K/V frags streamed by direct LDG
// from fragment-ordered global arrays. Only smem use: P staging (warp-private).
// Q tile 128 rows, KV tile 64; 8 warps, warp w owns q rows [w*16, w*16+16).
// ---------------------------------------------------------------------------
__global__ __launch_bounds__(256) void attn_frag_kernel(
    const uint32_t* __restrict__ Qh, const uint32_t* __restrict__ Ql,
    const uint32_t* __restrict__ Kh, const uint32_t* __restrict__ Kl,
    const uint32_t* __restrict__ Vf, const float* __restrict__ bias,
    float* __restrict__ out)
{
    __shared__ uint32_t sP[8192];   // 32 KB: [warp(8)][kblk(8)][lane(32)][reg(4)]

    const int tid  = threadIdx.x;
    const int lane = tid & 31;
    const int w    = tid >> 5;
    const int g    = lane >> 2;
    const int t    = lane & 3;
    const int mt = (CS / 128 - 1) - blockIdx.x;   // heavy tiles first
    const int h  = blockIdx.y, b = blockIdx.z;
    const int grp = h >> 2;
    const int m0 = mt * 128;

    // Q fragments for this warp's 16 rows: fb = mt*8 + w
    uint4 qH[4], qL[4];
    {
        size_t qb = ((size_t)(b * CNH + h) * (CS / 16) + (mt * 8 + w)) * 4;
#pragma unroll
        for (int ks = 0; ks < 4; ks++) {
            size_t ai = ((qb + ks) * 32 + lane) * 4;
            qH[ks] = *(const uint4*)(Qh + ai);
            qL[ks] = *(const uint4*)(Ql + ai);
        }
    }

    const size_t kb_base = (size_t)(b * CNKV + grp) * (CS / 8);
    const float* bb = bias + b * CS;

    float o[8][4];
    float m_i[2] = {-1e30f, -1e30f};
    float l_i[2] = {0.f, 0.f};
#pragma unroll
    for (int nf = 0; nf < 8; nf++)
#pragma unroll
        for (int r = 0; r < 4; r++) o[nf][r] = 0.f;

    const int ntmax = 2 * mt + 1;
    for (int nt = 0; nt <= ntmax; nt++) {
        const int n0 = nt * 64;

        // --- S = Q @ K^T (bf16-split 3-term), K frags direct from global ---
        float s[8][4];
#pragma unroll
        for (int nf = 0; nf < 8; nf++)
#pragma unroll
            for (int r = 0; r < 4; r++) s[nf][r] = 0.f;

#pragma unroll
        for (int ks = 0; ks < 4; ks++) {
#pragma unroll
            for (int nf = 0; nf < 8; nf++) {
                size_t bi = (((kb_base + nt * 8 + nf) * 4 + ks) * 32 + lane) * 2;
                uint2 bh = *(const uint2*)(Kh + bi);
                uint2 bl = *(const uint2*)(Kl + bi);
                mma_bf16(s[nf], qL[ks], bh);
                mma_bf16(s[nf], qH[ks], bl);
                mma_bf16(s[nf], qH[ks], bh);
            }
        }

        // --- bias (attention mask) for this tile's 16 columns of this lane ---
        float bv[8][2];
#pragma unroll
        for (int nf = 0; nf < 8; nf++)
#pragma unroll
            for (int e = 0; e < 2; e++)
                bv[nf][e] = bb[n0 + nf * 8 + 2 * t + e];

        // --- mask + online softmax (rows g, g+8 of this warp) ---
#pragma unroll
        for (int rh = 0; rh < 2; rh++) {
            const int ig = m0 + w * 16 + g + rh * 8;
            float rmax = -1e30f;
#pragma unroll
            for (int nf = 0; nf < 8; nf++)
#pragma unroll
                for (int e = 0; e < 2; e++) {
                    int jg = n0 + nf * 8 + 2 * t + e;
                    float val = s[nf][rh * 2 + e] * 0.125f + bv[nf][e];
                    if (jg > ig) val = -1e30f;
                    s[nf][rh * 2 + e] = val;
                    rmax = fmaxf(rmax, val);
                }
            rmax = fmaxf(rmax, __shfl_xor_sync(0xffffffffu, rmax, 1));
            rmax = fmaxf(rmax, __shfl_xor_sync(0xffffffffu, rmax, 2));
            float nm = fmaxf(m_i[rh], rmax);
            float corr = __expf(m_i[rh] - nm);
            m_i[rh] = nm;
            float rs = 0.f;
#pragma unroll
            for (int nf = 0; nf < 8; nf++)
#pragma unroll
                for (int e = 0; e < 2; e++) {
                    float p = __expf(s[nf][rh * 2 + e] - nm);
                    s[nf][rh * 2 + e] = p;
                    rs += p;
                }
            rs += __shfl_xor_sync(0xffffffffu, rs, 1);
            rs += __shfl_xor_sync(0xffffffffu, rs, 2);
            l_i[rh] = l_i[rh] * corr + rs;
#pragma unroll
            for (int nf = 0; nf < 8; nf++) {
                o[nf][rh * 2 + 0] *= corr;
                o[nf][rh * 2 + 1] *= corr;
            }
        }

        // --- stage P (tf32 A-frag, warp-private smem region) ---
#pragma unroll
        for (int nf = 0; nf < 8; nf++)
#pragma unroll
            for (int rh = 0; rh < 2; rh++)
#pragma unroll
                for (int e = 0; e < 2; e++) {
                    int c = 2 * t + e;
                    int ln = g * 4 + (c & 3);
                    int rg = rh + 2 * (c >> 2);
                    sP[((w * 8 + nf) * 32 + ln) * 4 + rg] = f2tf(s[nf][rh * 2 + e]);
                }
        __syncwarp();

        // --- O += P @ V (tf32), V frags direct from global ---
#pragma unroll
        for (int ks = 0; ks < 8; ks++) {
            uint4 aP = *(const uint4*)&sP[((w * 8 + ks) * 32 + lane) * 4];
#pragma unroll
            for (int nf = 0; nf < 8; nf++) {
                size_t vi = (((kb_base + nt * 8 + ks) * 8 + nf) * 32 + lane) * 2;
                uint2 bv2 = *(const uint2*)(Vf + vi);
                mma_tf32(o[nf], aP, bv2);
            }
        }
        __syncwarp();
    }

    // --- normalize and store (B, S, NH, HD) ---
    float inv0 = 1.0f / l_i[0];
    float inv1 = 1.0f / l_i[1];
    int row0 = m0 + w * 16 + g;
#pragma unroll
    for (int nf = 0; nf < 8; nf++) {
        int col = nf * 8 + 2 * t;
        *(float2*)(out + (((size_t)b * CS + row0) * CNH + h) * CHD + col) =
            make_float2(o[nf][0] * inv0, o[nf][1] * inv0);
        *(float2*)(out + (((size_t)b * CS + row0 + 8) * CNH + h) * CHD + col) =
            make_float2(o[nf][2] * inv1, o[nf][3] * inv1);
    }
}

// ---------------------------------------------------------------------------
extern "C" void kernel_launch(void* const* d_in, const int* in_sizes, int n_in,
                              void* d_out, int out_size)
{
    const float* x     = (const float*)d_in[0];
    const float* cosp  = (const float*)d_in[1];
    const float* sinp  = (const float*)d_in[2];
    const float* amask = (const float*)d_in[3];
    const float* Wq    = (const float*)d_in[4];
    const float* Wk    = (const float*)d_in[5];
    const float* Wv    = (const float*)d_in[6];
    const float* Wo    = (const float*)d_in[7];
    float* out = (float*)d_out;

    uint32_t *xh, *xl, *wh, *wl, *woh, *wol, *qfh, *qfl, *kfh, *kfl, *vf, *ah, *al;
    float *qkv, *bias, *attn;
    cudaGetSymbolAddress((void**)&xh, g_xh);
    cudaGetSymbolAddress((void**)&xl, g_xl);
    cudaGetSymbolAddress((void**)&wh, g_wh);
    cudaGetSymbolAddress((void**)&wl, g_wl);
    cudaGetSymbolAddress((void**)&woh, g_woh);
    cudaGetSymbolAddress((void**)&wol, g_wol);
    cudaGetSymbolAddress((void**)&qfh, g_qfh);
    cudaGetSymbolAddress((void**)&qfl, g_qfl);
    cudaGetSymbolAddress((void**)&kfh, g_kfh);
    cudaGetSymbolAddress((void**)&kfl, g_kfl);
    cudaGetSymbolAddress((void**)&vf, g_vf);
    cudaGetSymbolAddress((void**)&ah, g_ah);
    cudaGetSymbolAddress((void**)&al, g_al);
    cudaGetSymbolAddress((void**)&qkv, g_qkv);
    cudaGetSymbolAddress((void**)&bias, g_bias);
    cudaGetSymbolAddress((void**)&attn, g_attn);

    // 1. Split x into A-fragment order
    split_a_kernel<<<(CM * CH / 2 + 255) / 256, 256>>>(x, xh, xl, CM, CH);
    // 2. Split weights into B-fragment order (QKV fused into one array)
    split_b_kernel<<<((CH / 2) * (CNH * CHD) + 255) / 256, 256>>>(
        Wq, wh, wl, CH, CNH * CHD, 0);
    split_b_kernel<<<((CH / 2) * (CNKV * CHD) + 255) / 256, 256>>>(
        Wk, wh, wl, CH, CNKV * CHD, KOFF);
    split_b_kernel<<<((CH / 2) * (CNKV * CHD) + 255) / 256, 256>>>(
        Wv, wh, wl, CH, CNKV * CHD, VOFF);
    split_b_kernel<<<((CH / 2) * CH + 255) / 256, 256>>>(Wo, woh, wol, CH, CH, 0);

    // 3. Fused QKV projection
    gemm_frag_kernel<<<dim3(NQKV / 128, CM / 128), 256>>>(CM, NQKV, xh, xl, wh, wl, qkv);

    // 4. RoPE + layout conversion
    rope_split_q_kernel<<<(CB * CS * CNH * 16 + 255) / 256, 256>>>(
        qkv, cosp, sinp, qfh, qfl);
    rope_split_k_kernel<<<(CB * CS * CNKV * 16 + 255) / 256, 256>>>(
        qkv, cosp, sinp, kfh, kfl);
    conv_v_kernel<<<(CB * CS * CNKV * CHD + 255) / 256, 256>>>(qkv, amask, vf, bias);

    // 5. Attention
    attn_frag_kernel<<<dim3(CS / 128, CNH, CB), 256>>>(
        qfh, qfl, kfh, kfl, vf, bias, attn);

    // 6. Split attention output, then O-projection
    split_a_kernel<<<(CM * CH / 2 + 255) / 256, 256>>>(attn, ah, al, CM, CH);
    gemm_frag_kernel<<<dim3(CH / 128, CM / 128), 256>>>(CM, CH, ah, al, woh, wol, out);
}